// round 15
// baseline (speedup 1.0000x reference)
#include <cuda_runtime.h>
#include <cuda_fp16.h>
#include <cstdint>

#define B_  512
#define D_  1024
#define H1_ 512
#define H2_ 128

// ---- scratch (device globals: allocation-free rule) ----
__device__ float g_c1 [B_ * H1_];
__device__ float g_s1p[B_ * H1_];
__device__ float g_c3 [B_ * H1_];
__device__ float g_part2[4 * B_ * H2_];                // gemm2 split-K partials
__device__ __half g_b_frag[(size_t)D_ * H1_];          // W1 B-frags for jac/recover
__device__ float  g_w2_frag[H2_ * H1_];
__device__ __half g_c3_frag[B_ * H1_];
__device__ __half g_x_hi[(size_t)B_ * D_];             // x A-frags, hi/lo split
__device__ __half g_x_lo[(size_t)B_ * D_];
__device__ __half g_w1g1_hi[(size_t)H1_ * D_];         // W1 B-frags (gemm1 orient)
__device__ __half g_w1g1_lo[(size_t)H1_ * D_];

__device__ __forceinline__ float sigm(float v) { return 1.0f / (1.0f + expf(-v)); }

__device__ __forceinline__ uint32_t packh2(float a, float b) {
    __half2 t = __floats2half2_rn(a, b);
    return *reinterpret_cast<uint32_t*>(&t);
}
__device__ __forceinline__ void mma_f16(float* c, const uint32_t* a,
                                        uint32_t b0, uint32_t b1) {
    asm volatile("mma.sync.aligned.m16n8k16.row.col.f32.f16.f16.f32 "
                 "{%0,%1,%2,%3}, {%4,%5,%6,%7}, {%8,%9}, {%0,%1,%2,%3};"
                 : "+f"(c[0]), "+f"(c[1]), "+f"(c[2]), "+f"(c[3])
                 : "r"(a[0]), "r"(a[1]), "r"(a[2]), "r"(a[3]), "r"(b0), "r"(b1));
}

// ============================================================================
// x A-fragment pack with hi/lo fp16 split. Tiles [kt=64][mt=32], 512B each.
// ============================================================================
__global__ __launch_bounds__(256)
void x_frag_kernel(const float* __restrict__ x,
                   __half* __restrict__ xh, __half* __restrict__ xl) {
    const int t = blockIdx.x * 8 + (threadIdx.x >> 5);
    const int mt = t & 31, kt = t >> 5;
    const int lane = threadIdx.x & 31;
    const int r0 = mt * 16 + (lane >> 2);
    const int kb = kt * 16 + 2 * (lane & 3);
    const float* xa = x + (size_t)r0 * D_;
    const float* xb = xa + 8 * D_;
    float v[8] = {xa[kb], xa[kb + 1], xb[kb], xb[kb + 1],
                  xa[kb + 8], xa[kb + 9], xb[kb + 8], xb[kb + 9]};
    uint32_t hp[4], lp[4];
#pragma unroll
    for (int j = 0; j < 4; j++) {
        float a = v[2 * j], c = v[2 * j + 1];
        __half ha = __float2half_rn(a);
        __half hc = __float2half_rn(c);
        hp[j] = packh2(a, c);
        lp[j] = packh2(a - __half2float(ha), c - __half2float(hc));
    }
    *(uint4*)(xh + (size_t)t * 256 + lane * 8) = make_uint4(hp[0], hp[1], hp[2], hp[3]);
    *(uint4*)(xl + (size_t)t * 256 + lane * 8) = make_uint4(lp[0], lp[1], lp[2], lp[3]);
}

// ============================================================================
// W1 B-fragment pack for gemm1 (n=h1, k=d), hi/lo split. Tiles [n16=32][kt=64].
// ============================================================================
__global__ __launch_bounds__(256)
void w1g1_frag_kernel(const float* __restrict__ W1,
                      __half* __restrict__ wh, __half* __restrict__ wl) {
    const int t = blockIdx.x * 8 + (threadIdx.x >> 5);
    const int kt = t & 63, n16 = t >> 6;
    const int lane = threadIdx.x & 31;
    const int n0 = n16 * 16 + (lane >> 2);
    const int kb = kt * 16 + 2 * (lane & 3);
    const float* wa = W1 + (size_t)n0 * D_;
    const float* wb = wa + 8 * D_;
    float v[8] = {wa[kb], wa[kb + 1], wa[kb + 8], wa[kb + 9],
                  wb[kb], wb[kb + 1], wb[kb + 8], wb[kb + 9]};
    uint32_t hp[4], lp[4];
#pragma unroll
    for (int j = 0; j < 4; j++) {
        float a = v[2 * j], c = v[2 * j + 1];
        __half ha = __float2half_rn(a);
        __half hc = __float2half_rn(c);
        hp[j] = packh2(a, c);
        lp[j] = packh2(a - __half2float(ha), c - __half2float(hc));
    }
    const size_t off = ((size_t)n16 * 64 + kt) * 256 + lane * 8;
    *(uint4*)(wh + off) = make_uint4(hp[0], hp[1], hp[2], hp[3]);
    *(uint4*)(wl + off) = make_uint4(lp[0], lp[1], lp[2], lp[3]);
}

// ============================================================================
// gemm1 via mma.sync fp16 3-pass. c1/s1p fused epilogue. grid (8,16).
// ============================================================================
__global__ __launch_bounds__(256)
void gemm1_mma_kernel(const __half* __restrict__ xh, const __half* __restrict__ xl,
                      const __half* __restrict__ w1h, const __half* __restrict__ w1l,
                      const float* __restrict__ b1v,
                      float* __restrict__ c1, float* __restrict__ s1p) {
    const int tid = threadIdx.x;
    const int wid = tid >> 5;
    const int lane = tid & 31;
    const int wm = wid >> 2;
    const int wn = wid & 3;
    const int mtb = blockIdx.y * 2 + wm;
    const int n16 = blockIdx.x * 4 + wn;

    const __half* Ah = xh + (size_t)mtb * 256 + lane * 8;
    const __half* Al = xl + (size_t)mtb * 256 + lane * 8;
    const __half* Bh = w1h + (size_t)n16 * 64 * 256 + lane * 8;
    const __half* Bl = w1l + (size_t)n16 * 64 * 256 + lane * 8;

    float acc[2][4] = {};

    #pragma unroll 8
    for (int kt = 0; kt < 64; kt++) {
        uint4 ah = *(const uint4*)(Ah + (size_t)kt * 32 * 256);
        uint4 al = *(const uint4*)(Al + (size_t)kt * 32 * 256);
        uint4 bh = *(const uint4*)(Bh + (size_t)kt * 256);
        uint4 bl = *(const uint4*)(Bl + (size_t)kt * 256);
        const uint32_t* ap  = reinterpret_cast<const uint32_t*>(&ah);
        const uint32_t* alp = reinterpret_cast<const uint32_t*>(&al);
        mma_f16(acc[0], ap,  bh.x, bh.y);
        mma_f16(acc[1], ap,  bh.z, bh.w);
        mma_f16(acc[0], alp, bh.x, bh.y);
        mma_f16(acc[1], alp, bh.z, bh.w);
        mma_f16(acc[0], ap,  bl.x, bl.y);
        mma_f16(acc[1], ap,  bl.z, bl.w);
    }

    const int g = lane >> 2;
    const int cq = 2 * (lane & 3);
    const int r0 = mtb * 16 + g;
#pragma unroll
    for (int nt = 0; nt < 2; nt++) {
        const int col = n16 * 16 + nt * 8 + cq;
        const float b0 = b1v[col], b1c = b1v[col + 1];
        float cA = sigm(acc[nt][0] + b0);
        float cB = sigm(acc[nt][1] + b1c);
        float cC = sigm(acc[nt][2] + b0);
        float cD = sigm(acc[nt][3] + b1c);
        *(float2*)(c1  + (size_t)r0 * H1_ + col)       = make_float2(cA, cB);
        *(float2*)(c1  + (size_t)(r0 + 8) * H1_ + col) = make_float2(cC, cD);
        *(float2*)(s1p + (size_t)r0 * H1_ + col)       = make_float2(cA * (1.0f - cA), cB * (1.0f - cB));
        *(float2*)(s1p + (size_t)(r0 + 8) * H1_ + col) = make_float2(cC * (1.0f - cC), cD * (1.0f - cD));
    }
}

// ============================================================================
// B fragment pack: W1 -> g_b_frag (jac/recover orientation).
// ============================================================================
__global__ __launch_bounds__(256)
void w1_frag_kernel(const float* __restrict__ W1, __half* __restrict__ gB) {
    const int t = blockIdx.x * 8 + (threadIdx.x >> 5);
    const int n16 = t >> 5, kt = t & 31;
    const int lane = threadIdx.x & 31;
    const int n0 = n16 * 16 + (lane >> 2);
    const int kb = kt * 16 + 2 * (lane & 3);

    const float* Wk0 = W1 + (size_t)kb * D_;
    uint32_t p0 = packh2(Wk0[n0],              Wk0[D_ + n0]);
    uint32_t p1 = packh2(Wk0[8 * D_ + n0],     Wk0[9 * D_ + n0]);
    uint32_t p2 = packh2(Wk0[n0 + 8],          Wk0[D_ + n0 + 8]);
    uint32_t p3 = packh2(Wk0[8 * D_ + n0 + 8], Wk0[9 * D_ + n0 + 8]);

    *(uint4*)(gB + (size_t)t * 256 + lane * 8) = make_uint4(p0, p1, p2, p3);
}

// ============================================================================
// W2 fragment pre-permute (input-only, once).
// ============================================================================
__global__ __launch_bounds__(256)
void w2_frag_kernel(const float* __restrict__ W2, float* __restrict__ w2f) {
    const int kt = blockIdx.x;
    const int mt = threadIdx.x >> 5;
    const int lane = threadIdx.x & 31;
    const int r0 = mt * 16 + (lane >> 2);
    const int kb = kt * 16 + 2 * (lane & 3);
    const float* w2a = W2 + (size_t)r0 * H1_;
    const float* w2b = w2a + 8 * H1_;
    float* dst = w2f + ((size_t)kt * 8 + mt) * 256 + lane * 8;
    *(float4*)(dst)     = make_float4(w2a[kb],     w2a[kb + 1], w2b[kb],     w2b[kb + 1]);
    *(float4*)(dst + 4) = make_float4(w2a[kb + 8], w2a[kb + 9], w2b[kb + 8], w2b[kb + 9]);
}

// ============================================================================
// c3 fragment pack.
// ============================================================================
__global__ __launch_bounds__(256)
void c3_frag_kernel(const float* __restrict__ c3, __half* __restrict__ gA) {
    const int t = blockIdx.x * 8 + (threadIdx.x >> 5);
    const int kt = t >> 5, mt = t & 31;
    const int lane = threadIdx.x & 31;
    const int r0 = mt * 16 + (lane >> 2);
    const int kb = kt * 16 + 2 * (lane & 3);
    const float* ca = c3 + (size_t)r0 * H1_;
    const float* cb = ca + 8 * H1_;
    uint32_t p0 = packh2(ca[kb],     ca[kb + 1]);
    uint32_t p1 = packh2(cb[kb],     cb[kb + 1]);
    uint32_t p2 = packh2(ca[kb + 8], ca[kb + 9]);
    uint32_t p3 = packh2(cb[kb + 8], cb[kb + 9]);
    *(uint4*)(gA + (size_t)t * 256 + lane * 8) = make_uint4(p0, p1, p2, p3);
}

// ============================================================================
// Split-K partial SGEMM (TB) — gemm2 on the hidden stream.
// ============================================================================
__global__ __launch_bounds__(256)
void sgemm_part_kernel(const float* __restrict__ A, const float* __restrict__ Bm,
                       float* __restrict__ P, int M, int N, int K) {
    constexpr int BM = 64, BN = 64, BK = 16;
    __shared__ __align__(16) float As[BK][BM + 4];
    __shared__ __align__(16) float Bs[BK][BN + 4];

    const int tid = threadIdx.x;
    const int m0 = blockIdx.y * BM;
    const int n0 = blockIdx.x * BN;
    const int kbase = blockIdx.z * (K / 4);

    const int ak = tid & 15;
    const int am = tid >> 4;
    const int rowBase = (tid >> 4) * 4;
    const int colBase = (tid & 15) * 4;

    float acc[4][4] = {};
    float ra[4], rb[4];
    const int NT = (K / 4) / BK;

    auto loadA = [&](int t) {
        const int kt = kbase + t * BK;
#pragma unroll
        for (int j = 0; j < 4; j++)
            ra[j] = A[(size_t)(m0 + am + 16 * j) * K + kt + ak];
    };
    auto loadB = [&](int t) {
        const int kt = kbase + t * BK;
#pragma unroll
        for (int j = 0; j < 4; j++)
            rb[j] = Bm[(size_t)(n0 + am + 16 * j) * K + kt + ak];
    };
    auto storeAB = [&]() {
#pragma unroll
        for (int j = 0; j < 4; j++) As[ak][am + 16 * j] = ra[j];
#pragma unroll
        for (int j = 0; j < 4; j++) Bs[ak][am + 16 * j] = rb[j];
    };

    loadA(0); loadB(0);
    storeAB();
    __syncthreads();

    for (int t = 0; t < NT; t++) {
        if (t + 1 < NT) { loadA(t + 1); loadB(t + 1); }
#pragma unroll
        for (int kk = 0; kk < BK; kk++) {
            float a[4], bq[4];
            *(float4*)a  = *(const float4*)&As[kk][rowBase];
            *(float4*)bq = *(const float4*)&Bs[kk][colBase];
#pragma unroll
            for (int i = 0; i < 4; i++)
#pragma unroll
                for (int j = 0; j < 4; j++)
                    acc[i][j] += a[i] * bq[j];
        }
        __syncthreads();
        if (t + 1 < NT) { storeAB(); __syncthreads(); }
    }

    float* Pz = P + (size_t)blockIdx.z * M * N;
#pragma unroll
    for (int i = 0; i < 4; i++) {
        const int row = m0 + rowBase + i;
#pragma unroll
        for (int j = 0; j < 4; j++)
            Pz[(size_t)row * N + n0 + colBase + j] = acc[i][j];
    }
}

// ============================================================================
// Reduce 4 partials + bias -> sigmoid (c2 output, on s1).
// ============================================================================
__global__ __launch_bounds__(256)
void reduce_act_kernel(const float* __restrict__ P, const float* __restrict__ bias,
                       float* __restrict__ C, int MN, int Nmask) {
    const int idx = (blockIdx.x * 256 + threadIdx.x) * 4;
    float4 v0 = *(const float4*)(P + idx);
    float4 v1 = *(const float4*)(P + MN + idx);
    float4 v2 = *(const float4*)(P + 2 * MN + idx);
    float4 v3 = *(const float4*)(P + 3 * MN + idx);
    float4 bb = *(const float4*)(bias + (idx & Nmask));
    float4 c;
    c.x = sigm(v0.x + v1.x + v2.x + v3.x + bb.x);
    c.y = sigm(v0.y + v1.y + v2.y + v3.y + bb.y);
    c.z = sigm(v0.z + v1.z + v2.z + v3.z + bb.z);
    c.w = sigm(v0.w + v1.w + v2.w + v3.w + bb.w);
    *(float4*)(C + idx) = c;
}

// ============================================================================
// Jac GEMM (warp 64x64, CTA 128x256, 1 CTA/SM). s1p + c1 loaded in prologue;
// s2p computed SELF-CONTAINED post-mainloop from c1 row + W2 + b2 (removes
// the gemm2 dependency from the critical path). grid (4, 512).
// ============================================================================
__global__ __launch_bounds__(256, 1)
void jac_mma_kernel(const float* __restrict__ w2f,
                    const float* __restrict__ s1p,
                    const float* __restrict__ c1,
                    const float* __restrict__ W2,
                    const float* __restrict__ b2v,
                    const __half* __restrict__ gB,
                    float* __restrict__ jac) {
    __shared__ float ss[H1_];
    __shared__ float c1s[H1_];
    __shared__ float s2s[H2_];
    const int tid = threadIdx.x;
    const int wid = tid >> 5;
    const int lane = tid & 31;
    const int wm = wid >> 2;
    const int wn = wid & 3;
    const int b  = blockIdx.y;
    const int n0 = blockIdx.x * 256;

    for (int i = tid; i < H1_; i += 256) {
        ss[i]  = s1p[(size_t)b * H1_ + i];
        c1s[i] = c1[(size_t)b * H1_ + i];
    }
    __syncthreads();

    const float* Aw = w2f + (size_t)(wm * 4) * 256 + lane * 8;
    const __half* Bb = gB + (size_t)((n0 >> 4) + wn * 4) * (32 * 256) + lane * 8;
    const int klo = 2 * (lane & 3);

    float acc[4][8][4] = {};

    #pragma unroll 2
    for (int kt = 0; kt < 32; kt++) {
        const int kb = kt * 16 + klo;
        const float s0 = ss[kb], s1v = ss[kb + 1];
        const float s8 = ss[kb + 8], s9 = ss[kb + 9];

        uint32_t a[4][4];
        uint4 bv[4];
#pragma unroll
        for (int mt = 0; mt < 4; mt++) {
            const float* src = Aw + ((size_t)kt * 8 + mt) * 256;
            float4 f0 = *(const float4*)(src);
            float4 f1 = *(const float4*)(src + 4);
            a[mt][0] = packh2(f0.x * s0, f0.y * s1v);
            a[mt][1] = packh2(f0.z * s0, f0.w * s1v);
            a[mt][2] = packh2(f1.x * s8, f1.y * s9);
            a[mt][3] = packh2(f1.z * s8, f1.w * s9);
        }
#pragma unroll
        for (int np = 0; np < 4; np++)
            bv[np] = *(const uint4*)(Bb + ((size_t)np * 32 + kt) * 256);
#pragma unroll
        for (int mt = 0; mt < 4; mt++) {
#pragma unroll
            for (int np = 0; np < 4; np++) {
                mma_f16(acc[mt][np * 2 + 0], a[mt], bv[np].x, bv[np].y);
                mma_f16(acc[mt][np * 2 + 1], a[mt], bv[np].z, bv[np].w);
            }
        }
    }

    // ---- self-contained s2p: thread pair (2h, 2h+1) computes c2[b,h] ----
    {
        const int h = tid >> 1;
        const int half = tid & 1;
        const float* w2row = W2 + (size_t)h * H1_ + half * 256;
        const float* c1h = &c1s[half * 256];
        float accs = 0.0f;
#pragma unroll 8
        for (int c = 0; c < 256; c += 4) {
            float4 w = *(const float4*)(w2row + c);
            accs += w.x * c1h[c] + w.y * c1h[c + 1]
                  + w.z * c1h[c + 2] + w.w * c1h[c + 3];
        }
        accs += __shfl_xor_sync(0xffffffffu, accs, 1);
        if (half == 0) {
            float cc = sigm(accs + b2v[h]);
            s2s[h] = cc * (1.0f - cc);
        }
    }
    __syncthreads();

    const int g = lane >> 2;
    const int cq = 2 * (lane & 3);
#pragma unroll
    for (int mt = 0; mt < 4; mt++) {
        const int r0 = wm * 64 + mt * 16 + g;
        const float s0 = s2s[r0];
        const float s1 = s2s[r0 + 8];
        float* row0 = jac + ((size_t)b * H2_ + r0) * D_ + n0;
        float* row1 = row0 + 8 * D_;
#pragma unroll
        for (int nt = 0; nt < 8; nt++) {
            const int col = wn * 64 + nt * 8 + cq;
            *(float2*)(row0 + col) = make_float2(acc[mt][nt][0] * s0, acc[mt][nt][1] * s0);
            *(float2*)(row1 + col) = make_float2(acc[mt][nt][2] * s1, acc[mt][nt][3] * s1);
        }
    }
}

// ============================================================================
// recover = c3 @ W1 + b_r via fragment-direct mma; reuses g_b_frag.
// ============================================================================
__global__ __launch_bounds__(256, 1)
void recover_mma_kernel(const __half* __restrict__ gA,
                        const __half* __restrict__ gB,
                        const float* __restrict__ b_r,
                        float* __restrict__ out) {
    const int tid = threadIdx.x;
    const int wid = tid >> 5;
    const int lane = tid & 31;
    const int wm = wid >> 2;
    const int wn = wid & 3;
    const int m0 = blockIdx.y * 128;
    const int n0 = blockIdx.x * 256;

    const int mtb = (m0 >> 4) + wm * 4;
    const int n16base = (n0 >> 4) + wn * 4;

    float acc[4][8][4] = {};

    #pragma unroll 2
    for (int kt = 0; kt < 32; kt++) {
        uint4 av[4], bv[4];
#pragma unroll
        for (int mt = 0; mt < 4; mt++)
            av[mt] = *(const uint4*)(gA + ((size_t)kt * 32 + mtb + mt) * 256
                                     + lane * 8);
#pragma unroll
        for (int np = 0; np < 4; np++)
            bv[np] = *(const uint4*)(gB + ((size_t)(n16base + np) * 32 + kt) * 256
                                     + lane * 8);
#pragma unroll
        for (int mt = 0; mt < 4; mt++) {
            const uint32_t* ap = reinterpret_cast<const uint32_t*>(&av[mt]);
#pragma unroll
            for (int np = 0; np < 4; np++) {
                mma_f16(acc[mt][np * 2 + 0], ap, bv[np].x, bv[np].y);
                mma_f16(acc[mt][np * 2 + 1], ap, bv[np].z, bv[np].w);
            }
        }
    }

    const int g = lane >> 2;
    const int cq = 2 * (lane & 3);
#pragma unroll
    for (int mt = 0; mt < 4; mt++) {
        const int r0 = m0 + wm * 64 + mt * 16 + g;
        float* row0 = out + (size_t)r0 * D_ + n0;
        float* row1 = row0 + 8 * D_;
#pragma unroll
        for (int nt = 0; nt < 8; nt++) {
            const int col = wn * 64 + nt * 8 + cq;
            const float bc0 = b_r[n0 + col], bc1 = b_r[n0 + col + 1];
            *(float2*)(row0 + col) = make_float2(acc[mt][nt][0] + bc0, acc[mt][nt][1] + bc1);
            *(float2*)(row1 + col) = make_float2(acc[mt][nt][2] + bc0, acc[mt][nt][3] + bc1);
        }
    }
}

// ============================================================================
// Plain scalar SGEMM (gemm3: c3 = sigmoid(c2 @ W2 + b3), K=128).
// ============================================================================
__global__ __launch_bounds__(256)
void sgemm_nn_kernel(const float* __restrict__ A, const float* __restrict__ Bm,
                     const float* __restrict__ bias, float* __restrict__ C,
                     int M, int N, int K) {
    constexpr int BM = 64, BN = 64, BK = 16;
    __shared__ __align__(16) float As[BK][BM + 4];
    __shared__ __align__(16) float Bs[BK][BN + 4];

    const int tid = threadIdx.x;
    const int m0 = blockIdx.y * BM;
    const int n0 = blockIdx.x * BN;

    const int ak = tid & 15;
    const int am = tid >> 4;
    const int rowBase = (tid >> 4) * 4;
    const int colBase = (tid & 15) * 4;

    float acc[4][4] = {};
    float ra[4], rb[4];
    const int NT = K / BK;

    auto loadA = [&](int t) {
        const int kt = t * BK;
#pragma unroll
        for (int j = 0; j < 4; j++)
            ra[j] = A[(size_t)(m0 + am + 16 * j) * K + kt + ak];
    };
    auto loadB = [&](int t) {
        const int kt = t * BK;
#pragma unroll
        for (int j = 0; j < 4; j++)
            rb[j] = Bm[(size_t)(kt + (tid >> 6) + 4 * j) * N + n0 + (tid & 63)];
    };
    auto storeAB = [&]() {
#pragma unroll
        for (int j = 0; j < 4; j++) As[ak][am + 16 * j] = ra[j];
#pragma unroll
        for (int j = 0; j < 4; j++) Bs[(tid >> 6) + 4 * j][tid & 63] = rb[j];
    };

    loadA(0); loadB(0);
    storeAB();
    __syncthreads();

    for (int t = 0; t < NT; t++) {
        if (t + 1 < NT) { loadA(t + 1); loadB(t + 1); }
#pragma unroll
        for (int kk = 0; kk < BK; kk++) {
            float a[4], bq[4];
            *(float4*)a  = *(const float4*)&As[kk][rowBase];
            *(float4*)bq = *(const float4*)&Bs[kk][colBase];
#pragma unroll
            for (int i = 0; i < 4; i++)
#pragma unroll
                for (int j = 0; j < 4; j++)
                    acc[i][j] += a[i] * bq[j];
        }
        __syncthreads();
        if (t + 1 < NT) { storeAB(); __syncthreads(); }
    }

#pragma unroll
    for (int i = 0; i < 4; i++) {
        const int row = m0 + rowBase + i;
#pragma unroll
        for (int j = 0; j < 4; j++) {
            const int col = n0 + colBase + j;
            C[(size_t)row * N + col] = sigm(acc[i][j] + bias[col]);
        }
    }
}

// ============================================================================
// Streams/events (created once, on the first — non-captured — call).
// ============================================================================
struct Aux {
    cudaStream_t s1;
    cudaEvent_t e0, eg1, ew, ec1, etail;
    Aux() {
        cudaStreamCreateWithFlags(&s1, cudaStreamNonBlocking);
        cudaEventCreateWithFlags(&e0,   cudaEventDisableTiming);
        cudaEventCreateWithFlags(&eg1,  cudaEventDisableTiming);
        cudaEventCreateWithFlags(&ew,   cudaEventDisableTiming);
        cudaEventCreateWithFlags(&ec1,  cudaEventDisableTiming);
        cudaEventCreateWithFlags(&etail, cudaEventDisableTiming);
    }
};

extern "C" void kernel_launch(void* const* d_in, const int* in_sizes, int n_in,
                              void* d_out, int out_size) {
    const float* x   = (const float*)d_in[0];
    const float* W1  = (const float*)d_in[1];
    const float* b1  = (const float*)d_in[2];
    const float* W2  = (const float*)d_in[3];
    const float* b2  = (const float*)d_in[4];
    const float* b3  = (const float*)d_in[5];
    const float* b_r = (const float*)d_in[6];

    float* out     = (float*)d_out;
    float* recover = out;
    float* c2      = out + (size_t)B_ * D_;
    float* jac     = c2 + (size_t)B_ * H2_;

    float *c1, *s1p, *c3, *w2f, *p2;
    __half *b_frag, *c3_frag, *xh, *xl, *w1g1h, *w1g1l;
    cudaGetSymbolAddress((void**)&c1,  g_c1);
    cudaGetSymbolAddress((void**)&s1p, g_s1p);
    cudaGetSymbolAddress((void**)&c3,  g_c3);
    cudaGetSymbolAddress((void**)&w2f, g_w2_frag);
    cudaGetSymbolAddress((void**)&p2,  g_part2);
    cudaGetSymbolAddress((void**)&b_frag, g_b_frag);
    cudaGetSymbolAddress((void**)&c3_frag, g_c3_frag);
    cudaGetSymbolAddress((void**)&xh, g_x_hi);
    cudaGetSymbolAddress((void**)&xl, g_x_lo);
    cudaGetSymbolAddress((void**)&w1g1h, g_w1g1_hi);
    cudaGetSymbolAddress((void**)&w1g1l, g_w1g1_lo);

    static Aux aux;
    cudaStream_t s0 = 0, s1 = aux.s1;
    dim3 blk(256);

    // fork
    cudaEventRecord(aux.e0, s0);
    cudaStreamWaitEvent(s1, aux.e0, 0);

    // s1: input-only fragment preps (gemm1 B first — needed earliest)
    w1g1_frag_kernel<<<256, blk, 0, s1>>>(W1, w1g1h, w1g1l);
    cudaEventRecord(aux.eg1, s1);
    w1_frag_kernel<<<(64 * 32) / 8, blk, 0, s1>>>(W1, b_frag);
    w2_frag_kernel<<<32, blk, 0, s1>>>(W2, w2f);
    cudaEventRecord(aux.ew, s1);

    // s0: x fragments, then gemm1 on HMMA -> c1, s1p
    x_frag_kernel<<<256, blk, 0, s0>>>(x, xh, xl);
    cudaStreamWaitEvent(s0, aux.eg1, 0);
    gemm1_mma_kernel<<<dim3(8, 16), blk, 0, s0>>>(xh, xl, w1g1h, w1g1l,
                                                  b1, c1, s1p);
    cudaEventRecord(aux.ec1, s0);

    // s1 tail: gemm2 -> c2 output -> c3 chain -> recover (all hidden under jac)
    cudaStreamWaitEvent(s1, aux.ec1, 0);
    sgemm_part_kernel<<<dim3(H2_ / 64, B_ / 64, 4), blk, 0, s1>>>(
        c1, W2, p2, B_, H2_, H1_);
    reduce_act_kernel<<<(B_ * H2_) / 1024, blk, 0, s1>>>(
        p2, b2, c2, B_ * H2_, H2_ - 1);
    sgemm_nn_kernel<<<dim3(H1_ / 64, B_ / 64), blk, 0, s1>>>(
        c2, W2, b3, c3, B_, H1_, H2_);
    c3_frag_kernel<<<(32 * 32) / 8, blk, 0, s1>>>(c3, c3_frag);
    recover_mma_kernel<<<dim3(D_ / 256, B_ / 128), blk, 0, s1>>>(
        c3_frag, b_frag, b_r, recover);
    cudaEventRecord(aux.etail, s1);

    // s0: jac directly after gemm1 (self-contained s2p; no gemm2 dependency)
    cudaStreamWaitEvent(s0, aux.ew, 0);
    jac_mma_kernel<<<dim3(D_ / 256, B_), blk, 0, s0>>>(
        w2f, s1p, c1, W2, b2, b_frag, jac);

    // join
    cudaStreamWaitEvent(s0, aux.etail, 0);
}

// round 16
// speedup vs baseline: 1.3972x; 1.3972x over previous
#include <cuda_runtime.h>
#include <cuda_fp16.h>
#include <cstdint>

#define B_  512
#define D_  1024
#define H1_ 512
#define H2_ 128

// ---- scratch (device globals: allocation-free rule) ----
__device__ float g_c1 [B_ * H1_];
__device__ float g_s1p[B_ * H1_];
__device__ float g_c3 [B_ * H1_];
__device__ float g_part2[4 * B_ * H2_];                // gemm2 split-K partials
__device__ __half g_b_frag[(size_t)D_ * H1_];          // W1 B-frags for jac/recover
__device__ float  g_w2_frag[H2_ * H1_];
__device__ __half g_c3_frag[B_ * H1_];

__device__ __forceinline__ float sigm(float v) { return 1.0f / (1.0f + expf(-v)); }

__device__ __forceinline__ uint32_t packh2(float a, float b) {
    __half2 t = __floats2half2_rn(a, b);
    return *reinterpret_cast<uint32_t*>(&t);
}
// hi = fp16(a,b); lo = fp16(a - fp16(a), b - fp16(b))   (same order as R14 preps)
__device__ __forceinline__ void packh2_hilo(float a, float b,
                                            uint32_t& hi, uint32_t& lo) {
    __half ha = __float2half_rn(a);
    __half hb = __float2half_rn(b);
    hi = packh2(a, b);
    lo = packh2(a - __half2float(ha), b - __half2float(hb));
}
__device__ __forceinline__ void mma_f16(float* c, const uint32_t* a,
                                        uint32_t b0, uint32_t b1) {
    asm volatile("mma.sync.aligned.m16n8k16.row.col.f32.f16.f16.f32 "
                 "{%0,%1,%2,%3}, {%4,%5,%6,%7}, {%8,%9}, {%0,%1,%2,%3};"
                 : "+f"(c[0]), "+f"(c[1]), "+f"(c[2]), "+f"(c[3])
                 : "r"(a[0]), "r"(a[1]), "r"(a[2]), "r"(a[3]), "r"(b0), "r"(b1));
}

// ============================================================================
// gemm1 via mma.sync fp16 3-pass (AhBh + AlBh + AhBl), operands converted
// ON THE FLY from f32 x and W1 (no prep kernels, zero dependencies).
// c1 = sigmoid(x @ W1^T + b1), s1p fused in epilogue.
// CTA 32x64, warp tile 16x16, grid (8, 16) = 128 CTAs.
// ============================================================================
__global__ __launch_bounds__(256)
void gemm1_mma_kernel(const float* __restrict__ x, const float* __restrict__ W1,
                      const float* __restrict__ b1v,
                      float* __restrict__ c1, float* __restrict__ s1p) {
    const int tid = threadIdx.x;
    const int wid = tid >> 5;
    const int lane = tid & 31;
    const int wm = wid >> 2;           // 0..1
    const int wn = wid & 3;            // 0..3
    const int mtb = blockIdx.y * 2 + wm;     // 16-row tile (0..31)
    const int n16 = blockIdx.x * 4 + wn;     // 16-col tile (0..31)

    const float* xa = x  + (size_t)(mtb * 16 + (lane >> 2)) * D_ + 2 * (lane & 3);
    const float* xb = xa + 8 * D_;
    const float* wa = W1 + (size_t)(n16 * 16 + (lane >> 2)) * D_ + 2 * (lane & 3);
    const float* wb = wa + 8 * D_;

    float acc[2][4] = {};

    #pragma unroll 4
    for (int kt = 0; kt < 64; kt++) {
        const int kb = kt * 16;
        float2 x0 = *(const float2*)(xa + kb);
        float2 x1 = *(const float2*)(xb + kb);
        float2 x2 = *(const float2*)(xa + kb + 8);
        float2 x3 = *(const float2*)(xb + kb + 8);
        float2 w0 = *(const float2*)(wa + kb);
        float2 w1 = *(const float2*)(wa + kb + 8);
        float2 w2 = *(const float2*)(wb + kb);
        float2 w3 = *(const float2*)(wb + kb + 8);

        uint32_t ah[4], al[4];
        packh2_hilo(x0.x, x0.y, ah[0], al[0]);
        packh2_hilo(x1.x, x1.y, ah[1], al[1]);
        packh2_hilo(x2.x, x2.y, ah[2], al[2]);
        packh2_hilo(x3.x, x3.y, ah[3], al[3]);

        uint32_t bh[4], bl[4];
        packh2_hilo(w0.x, w0.y, bh[0], bl[0]);
        packh2_hilo(w1.x, w1.y, bh[1], bl[1]);
        packh2_hilo(w2.x, w2.y, bh[2], bl[2]);
        packh2_hilo(w3.x, w3.y, bh[3], bl[3]);

        mma_f16(acc[0], ah, bh[0], bh[1]);
        mma_f16(acc[1], ah, bh[2], bh[3]);
        mma_f16(acc[0], al, bh[0], bh[1]);
        mma_f16(acc[1], al, bh[2], bh[3]);
        mma_f16(acc[0], ah, bl[0], bl[1]);
        mma_f16(acc[1], ah, bl[2], bl[3]);
    }

    const int g = lane >> 2;
    const int cq = 2 * (lane & 3);
    const int r0 = mtb * 16 + g;
#pragma unroll
    for (int nt = 0; nt < 2; nt++) {
        const int col = n16 * 16 + nt * 8 + cq;
        const float b0 = b1v[col], b1c = b1v[col + 1];
        float cA = sigm(acc[nt][0] + b0);
        float cB = sigm(acc[nt][1] + b1c);
        float cC = sigm(acc[nt][2] + b0);
        float cD = sigm(acc[nt][3] + b1c);
        *(float2*)(c1  + (size_t)r0 * H1_ + col)       = make_float2(cA, cB);
        *(float2*)(c1  + (size_t)(r0 + 8) * H1_ + col) = make_float2(cC, cD);
        *(float2*)(s1p + (size_t)r0 * H1_ + col)       = make_float2(cA * (1.0f - cA), cB * (1.0f - cB));
        *(float2*)(s1p + (size_t)(r0 + 8) * H1_ + col) = make_float2(cC * (1.0f - cC), cD * (1.0f - cD));
    }
}

// ============================================================================
// B fragment pack: W1 -> g_b_frag (jac/recover orientation).
// ============================================================================
__global__ __launch_bounds__(256)
void w1_frag_kernel(const float* __restrict__ W1, __half* __restrict__ gB) {
    const int t = blockIdx.x * 8 + (threadIdx.x >> 5);
    const int n16 = t >> 5, kt = t & 31;
    const int lane = threadIdx.x & 31;
    const int n0 = n16 * 16 + (lane >> 2);
    const int kb = kt * 16 + 2 * (lane & 3);

    const float* Wk0 = W1 + (size_t)kb * D_;
    uint32_t p0 = packh2(Wk0[n0],              Wk0[D_ + n0]);
    uint32_t p1 = packh2(Wk0[8 * D_ + n0],     Wk0[9 * D_ + n0]);
    uint32_t p2 = packh2(Wk0[n0 + 8],          Wk0[D_ + n0 + 8]);
    uint32_t p3 = packh2(Wk0[8 * D_ + n0 + 8], Wk0[9 * D_ + n0 + 8]);

    *(uint4*)(gB + (size_t)t * 256 + lane * 8) = make_uint4(p0, p1, p2, p3);
}

// ============================================================================
// W2 fragment pre-permute (input-only, once).
// ============================================================================
__global__ __launch_bounds__(256)
void w2_frag_kernel(const float* __restrict__ W2, float* __restrict__ w2f) {
    const int kt = blockIdx.x;
    const int mt = threadIdx.x >> 5;
    const int lane = threadIdx.x & 31;
    const int r0 = mt * 16 + (lane >> 2);
    const int kb = kt * 16 + 2 * (lane & 3);
    const float* w2a = W2 + (size_t)r0 * H1_;
    const float* w2b = w2a + 8 * H1_;
    float* dst = w2f + ((size_t)kt * 8 + mt) * 256 + lane * 8;
    *(float4*)(dst)     = make_float4(w2a[kb],     w2a[kb + 1], w2b[kb],     w2b[kb + 1]);
    *(float4*)(dst + 4) = make_float4(w2a[kb + 8], w2a[kb + 9], w2b[kb + 8], w2b[kb + 9]);
}

// ============================================================================
// c3 fragment pack.
// ============================================================================
__global__ __launch_bounds__(256)
void c3_frag_kernel(const float* __restrict__ c3, __half* __restrict__ gA) {
    const int t = blockIdx.x * 8 + (threadIdx.x >> 5);
    const int kt = t >> 5, mt = t & 31;
    const int lane = threadIdx.x & 31;
    const int r0 = mt * 16 + (lane >> 2);
    const int kb = kt * 16 + 2 * (lane & 3);
    const float* ca = c3 + (size_t)r0 * H1_;
    const float* cb = ca + 8 * H1_;
    uint32_t p0 = packh2(ca[kb],     ca[kb + 1]);
    uint32_t p1 = packh2(cb[kb],     cb[kb + 1]);
    uint32_t p2 = packh2(ca[kb + 8], ca[kb + 9]);
    uint32_t p3 = packh2(cb[kb + 8], cb[kb + 9]);
    *(uint4*)(gA + (size_t)t * 256 + lane * 8) = make_uint4(p0, p1, p2, p3);
}

// ============================================================================
// Split-K partial SGEMM (TB): gemm2 (c1 @ W2^T) -> p2.
// ============================================================================
__global__ __launch_bounds__(256)
void sgemm_part_kernel(const float* __restrict__ A, const float* __restrict__ Bm,
                       float* __restrict__ P, int M, int N, int K) {
    constexpr int BM = 64, BN = 64, BK = 16;
    __shared__ __align__(16) float As[BK][BM + 4];
    __shared__ __align__(16) float Bs[BK][BN + 4];

    const int tid = threadIdx.x;
    const int m0 = blockIdx.y * BM;
    const int n0 = blockIdx.x * BN;
    const int kbase = blockIdx.z * (K / 4);

    const int ak = tid & 15;
    const int am = tid >> 4;
    const int rowBase = (tid >> 4) * 4;
    const int colBase = (tid & 15) * 4;

    float acc[4][4] = {};
    float ra[4], rb[4];
    const int NT = (K / 4) / BK;

    auto loadA = [&](int t) {
        const int kt = kbase + t * BK;
#pragma unroll
        for (int j = 0; j < 4; j++)
            ra[j] = A[(size_t)(m0 + am + 16 * j) * K + kt + ak];
    };
    auto loadB = [&](int t) {
        const int kt = kbase + t * BK;
#pragma unroll
        for (int j = 0; j < 4; j++)
            rb[j] = Bm[(size_t)(n0 + am + 16 * j) * K + kt + ak];
    };
    auto storeAB = [&]() {
#pragma unroll
        for (int j = 0; j < 4; j++) As[ak][am + 16 * j] = ra[j];
#pragma unroll
        for (int j = 0; j < 4; j++) Bs[ak][am + 16 * j] = rb[j];
    };

    loadA(0); loadB(0);
    storeAB();
    __syncthreads();

    for (int t = 0; t < NT; t++) {
        if (t + 1 < NT) { loadA(t + 1); loadB(t + 1); }
#pragma unroll
        for (int kk = 0; kk < BK; kk++) {
            float a[4], bq[4];
            *(float4*)a  = *(const float4*)&As[kk][rowBase];
            *(float4*)bq = *(const float4*)&Bs[kk][colBase];
#pragma unroll
            for (int i = 0; i < 4; i++)
#pragma unroll
                for (int j = 0; j < 4; j++)
                    acc[i][j] += a[i] * bq[j];
        }
        __syncthreads();
        if (t + 1 < NT) { storeAB(); __syncthreads(); }
    }

    float* Pz = P + (size_t)blockIdx.z * M * N;
#pragma unroll
    for (int i = 0; i < 4; i++) {
        const int row = m0 + rowBase + i;
#pragma unroll
        for (int j = 0; j < 4; j++)
            Pz[(size_t)row * N + n0 + colBase + j] = acc[i][j];
    }
}

// ============================================================================
// Reduce 4 partials + bias -> sigmoid (c2 output, on s1).
// ============================================================================
__global__ __launch_bounds__(256)
void reduce_act_kernel(const float* __restrict__ P, const float* __restrict__ bias,
                       float* __restrict__ C, int MN, int Nmask) {
    const int idx = (blockIdx.x * 256 + threadIdx.x) * 4;
    float4 v0 = *(const float4*)(P + idx);
    float4 v1 = *(const float4*)(P + MN + idx);
    float4 v2 = *(const float4*)(P + 2 * MN + idx);
    float4 v3 = *(const float4*)(P + 3 * MN + idx);
    float4 bb = *(const float4*)(bias + (idx & Nmask));
    float4 c;
    c.x = sigm(v0.x + v1.x + v2.x + v3.x + bb.x);
    c.y = sigm(v0.y + v1.y + v2.y + v3.y + bb.y);
    c.z = sigm(v0.z + v1.z + v2.z + v3.z + bb.z);
    c.w = sigm(v0.w + v1.w + v2.w + v3.w + bb.w);
    *(float4*)(C + idx) = c;
}

// ============================================================================
// Jac GEMM — EXACT R14 version (warp 64x64, CTA 128x256, 1 CTA/SM).
// s1p loaded directly; s2p from p2 partials in prologue. grid (4, 512).
// ============================================================================
__global__ __launch_bounds__(256, 1)
void jac_mma_kernel(const float* __restrict__ w2f,
                    const float* __restrict__ s1p,
                    const float* __restrict__ p2, const float* __restrict__ b2v,
                    const __half* __restrict__ gB,
                    float* __restrict__ jac) {
    __shared__ float ss[H1_];
    __shared__ float s2s[H2_];
    constexpr int MN2 = B_ * H2_;
    const int tid = threadIdx.x;
    const int wid = tid >> 5;
    const int lane = tid & 31;
    const int wm = wid >> 2;
    const int wn = wid & 3;
    const int b  = blockIdx.y;
    const int n0 = blockIdx.x * 256;

    for (int i = tid; i < H1_; i += 256) ss[i] = s1p[(size_t)b * H1_ + i];
    if (tid < H2_) {
        const int off = b * H2_ + tid;
        float v = p2[off] + p2[MN2 + off] + p2[2 * MN2 + off]
                + p2[3 * MN2 + off] + b2v[tid];
        float c = sigm(v);
        s2s[tid] = c * (1.0f - c);
    }
    __syncthreads();

    const float* Aw = w2f + (size_t)(wm * 4) * 256 + lane * 8;
    const __half* Bb = gB + (size_t)((n0 >> 4) + wn * 4) * (32 * 256) + lane * 8;
    const int klo = 2 * (lane & 3);

    float acc[4][8][4] = {};

    #pragma unroll 2
    for (int kt = 0; kt < 32; kt++) {
        const int kb = kt * 16 + klo;
        const float s0 = ss[kb], s1v = ss[kb + 1];
        const float s8 = ss[kb + 8], s9 = ss[kb + 9];

        uint32_t a[4][4];
        uint4 bv[4];
#pragma unroll
        for (int mt = 0; mt < 4; mt++) {
            const float* src = Aw + ((size_t)kt * 8 + mt) * 256;
            float4 f0 = *(const float4*)(src);
            float4 f1 = *(const float4*)(src + 4);
            a[mt][0] = packh2(f0.x * s0, f0.y * s1v);
            a[mt][1] = packh2(f0.z * s0, f0.w * s1v);
            a[mt][2] = packh2(f1.x * s8, f1.y * s9);
            a[mt][3] = packh2(f1.z * s8, f1.w * s9);
        }
#pragma unroll
        for (int np = 0; np < 4; np++)
            bv[np] = *(const uint4*)(Bb + ((size_t)np * 32 + kt) * 256);
#pragma unroll
        for (int mt = 0; mt < 4; mt++) {
#pragma unroll
            for (int np = 0; np < 4; np++) {
                mma_f16(acc[mt][np * 2 + 0], a[mt], bv[np].x, bv[np].y);
                mma_f16(acc[mt][np * 2 + 1], a[mt], bv[np].z, bv[np].w);
            }
        }
    }

    const int g = lane >> 2;
    const int cq = 2 * (lane & 3);
#pragma unroll
    for (int mt = 0; mt < 4; mt++) {
        const int r0 = wm * 64 + mt * 16 + g;
        const float s0 = s2s[r0];
        const float s1 = s2s[r0 + 8];
        float* row0 = jac + ((size_t)b * H2_ + r0) * D_ + n0;
        float* row1 = row0 + 8 * D_;
#pragma unroll
        for (int nt = 0; nt < 8; nt++) {
            const int col = wn * 64 + nt * 8 + cq;
            *(float2*)(row0 + col) = make_float2(acc[mt][nt][0] * s0, acc[mt][nt][1] * s0);
            *(float2*)(row1 + col) = make_float2(acc[mt][nt][2] * s1, acc[mt][nt][3] * s1);
        }
    }
}

// ============================================================================
// recover = c3 @ W1 + b_r via fragment-direct mma; reuses g_b_frag.
// ============================================================================
__global__ __launch_bounds__(256, 1)
void recover_mma_kernel(const __half* __restrict__ gA,
                        const __half* __restrict__ gB,
                        const float* __restrict__ b_r,
                        float* __restrict__ out) {
    const int tid = threadIdx.x;
    const int wid = tid >> 5;
    const int lane = tid & 31;
    const int wm = wid >> 2;
    const int wn = wid & 3;
    const int m0 = blockIdx.y * 128;
    const int n0 = blockIdx.x * 256;

    const int mtb = (m0 >> 4) + wm * 4;
    const int n16base = (n0 >> 4) + wn * 4;

    float acc[4][8][4] = {};

    #pragma unroll 2
    for (int kt = 0; kt < 32; kt++) {
        uint4 av[4], bv[4];
#pragma unroll
        for (int mt = 0; mt < 4; mt++)
            av[mt] = *(const uint4*)(gA + ((size_t)kt * 32 + mtb + mt) * 256
                                     + lane * 8);
#pragma unroll
        for (int np = 0; np < 4; np++)
            bv[np] = *(const uint4*)(gB + ((size_t)(n16base + np) * 32 + kt) * 256
                                     + lane * 8);
#pragma unroll
        for (int mt = 0; mt < 4; mt++) {
            const uint32_t* ap = reinterpret_cast<const uint32_t*>(&av[mt]);
#pragma unroll
            for (int np = 0; np < 4; np++) {
                mma_f16(acc[mt][np * 2 + 0], ap, bv[np].x, bv[np].y);
                mma_f16(acc[mt][np * 2 + 1], ap, bv[np].z, bv[np].w);
            }
        }
    }

    const int g = lane >> 2;
    const int cq = 2 * (lane & 3);
#pragma unroll
    for (int mt = 0; mt < 4; mt++) {
        const int r0 = m0 + wm * 64 + mt * 16 + g;
        float* row0 = out + (size_t)r0 * D_ + n0;
        float* row1 = row0 + 8 * D_;
#pragma unroll
        for (int nt = 0; nt < 8; nt++) {
            const int col = wn * 64 + nt * 8 + cq;
            const float bc0 = b_r[n0 + col], bc1 = b_r[n0 + col + 1];
            *(float2*)(row0 + col) = make_float2(acc[mt][nt][0] + bc0, acc[mt][nt][1] + bc1);
            *(float2*)(row1 + col) = make_float2(acc[mt][nt][2] + bc0, acc[mt][nt][3] + bc1);
        }
    }
}

// ============================================================================
// Plain scalar SGEMM (gemm3: c3 = sigmoid(c2 @ W2 + b3), K=128).
// ============================================================================
__global__ __launch_bounds__(256)
void sgemm_nn_kernel(const float* __restrict__ A, const float* __restrict__ Bm,
                     const float* __restrict__ bias, float* __restrict__ C,
                     int M, int N, int K) {
    constexpr int BM = 64, BN = 64, BK = 16;
    __shared__ __align__(16) float As[BK][BM + 4];
    __shared__ __align__(16) float Bs[BK][BN + 4];

    const int tid = threadIdx.x;
    const int m0 = blockIdx.y * BM;
    const int n0 = blockIdx.x * BN;

    const int ak = tid & 15;
    const int am = tid >> 4;
    const int rowBase = (tid >> 4) * 4;
    const int colBase = (tid & 15) * 4;

    float acc[4][4] = {};
    float ra[4], rb[4];
    const int NT = K / BK;

    auto loadA = [&](int t) {
        const int kt = t * BK;
#pragma unroll
        for (int j = 0; j < 4; j++)
            ra[j] = A[(size_t)(m0 + am + 16 * j) * K + kt + ak];
    };
    auto loadB = [&](int t) {
        const int kt = t * BK;
#pragma unroll
        for (int j = 0; j < 4; j++)
            rb[j] = Bm[(size_t)(kt + (tid >> 6) + 4 * j) * N + n0 + (tid & 63)];
    };
    auto storeAB = [&]() {
#pragma unroll
        for (int j = 0; j < 4; j++) As[ak][am + 16 * j] = ra[j];
#pragma unroll
        for (int j = 0; j < 4; j++) Bs[(tid >> 6) + 4 * j][tid & 63] = rb[j];
    };

    loadA(0); loadB(0);
    storeAB();
    __syncthreads();

    for (int t = 0; t < NT; t++) {
        if (t + 1 < NT) { loadA(t + 1); loadB(t + 1); }
#pragma unroll
        for (int kk = 0; kk < BK; kk++) {
            float a[4], bq[4];
            *(float4*)a  = *(const float4*)&As[kk][rowBase];
            *(float4*)bq = *(const float4*)&Bs[kk][colBase];
#pragma unroll
            for (int i = 0; i < 4; i++)
#pragma unroll
                for (int j = 0; j < 4; j++)
                    acc[i][j] += a[i] * bq[j];
        }
        __syncthreads();
        if (t + 1 < NT) { storeAB(); __syncthreads(); }
    }

#pragma unroll
    for (int i = 0; i < 4; i++) {
        const int row = m0 + rowBase + i;
#pragma unroll
        for (int j = 0; j < 4; j++) {
            const int col = n0 + colBase + j;
            C[(size_t)row * N + col] = sigm(acc[i][j] + bias[col]);
        }
    }
}

// ============================================================================
// Streams/events (created once, on the first — non-captured — call).
// ============================================================================
struct Aux {
    cudaStream_t s1;
    cudaEvent_t e0, ew, ep2, etail;
    Aux() {
        cudaStreamCreateWithFlags(&s1, cudaStreamNonBlocking);
        cudaEventCreateWithFlags(&e0,   cudaEventDisableTiming);
        cudaEventCreateWithFlags(&ew,   cudaEventDisableTiming);
        cudaEventCreateWithFlags(&ep2,  cudaEventDisableTiming);
        cudaEventCreateWithFlags(&etail, cudaEventDisableTiming);
    }
};

extern "C" void kernel_launch(void* const* d_in, const int* in_sizes, int n_in,
                              void* d_out, int out_size) {
    const float* x   = (const float*)d_in[0];
    const float* W1  = (const float*)d_in[1];
    const float* b1  = (const float*)d_in[2];
    const float* W2  = (const float*)d_in[3];
    const float* b2  = (const float*)d_in[4];
    const float* b3  = (const float*)d_in[5];
    const float* b_r = (const float*)d_in[6];

    float* out     = (float*)d_out;
    float* recover = out;
    float* c2      = out + (size_t)B_ * D_;
    float* jac     = c2 + (size_t)B_ * H2_;

    float *c1, *s1p, *c3, *w2f, *p2;
    __half *b_frag, *c3_frag;
    cudaGetSymbolAddress((void**)&c1,  g_c1);
    cudaGetSymbolAddress((void**)&s1p, g_s1p);
    cudaGetSymbolAddress((void**)&c3,  g_c3);
    cudaGetSymbolAddress((void**)&w2f, g_w2_frag);
    cudaGetSymbolAddress((void**)&p2,  g_part2);
    cudaGetSymbolAddress((void**)&b_frag, g_b_frag);
    cudaGetSymbolAddress((void**)&c3_frag, g_c3_frag);

    static Aux aux;
    cudaStream_t s0 = 0, s1 = aux.s1;
    dim3 blk(256);

    // fork
    cudaEventRecord(aux.e0, s0);
    cudaStreamWaitEvent(s1, aux.e0, 0);

    // s1: jac/recover operand preps (hidden under gemm1+gemm2)
    w1_frag_kernel<<<(64 * 32) / 8, blk, 0, s1>>>(W1, b_frag);
    w2_frag_kernel<<<32, blk, 0, s1>>>(W2, w2f);
    cudaEventRecord(aux.ew, s1);

    // s0: gemm1 (zero deps, on-the-fly conversion) -> c1, s1p
    gemm1_mma_kernel<<<dim3(8, 16), blk, 0, s0>>>(x, W1, b1, c1, s1p);

    // s0: gemm2 split-K -> p2
    sgemm_part_kernel<<<dim3(H2_ / 64, B_ / 64, 4), blk, 0, s0>>>(
        c1, W2, p2, B_, H2_, H1_);
    cudaEventRecord(aux.ep2, s0);

    // s1 tail: c2 output -> c3 chain -> recover (hidden under jac)
    cudaStreamWaitEvent(s1, aux.ep2, 0);
    reduce_act_kernel<<<(B_ * H2_) / 1024, blk, 0, s1>>>(
        p2, b2, c2, B_ * H2_, H2_ - 1);
    sgemm_nn_kernel<<<dim3(H1_ / 64, B_ / 64), blk, 0, s1>>>(
        c2, W2, b3, c3, B_, H1_, H2_);
    c3_frag_kernel<<<(32 * 32) / 8, blk, 0, s1>>>(c3, c3_frag);
    recover_mma_kernel<<<dim3(D_ / 256, B_ / 128), blk, 0, s1>>>(
        c3_frag, b_frag, b_r, recover);
    cudaEventRecord(aux.etail, s1);

    // s0: jac (s1p direct; s2p from p2 in prologue)
    cudaStreamWaitEvent(s0, aux.ew, 0);
    jac_mma_kernel<<<dim3(D_ / 256, B_), blk, 0, s0>>>(
        w2f, s1p, p2, b2, b_frag, jac);

    // join
    cudaStreamWaitEvent(s0, aux.etail, 0);
}

// round 17
// speedup vs baseline: 1.4809x; 1.0600x over previous
#include <cuda_runtime.h>
#include <cuda_fp16.h>
#include <cstdint>

#define B_  512
#define D_  1024
#define H1_ 512
#define H2_ 128
#define SK2 8                                          // gemm2 split-K factor

// ---- scratch (device globals: allocation-free rule) ----
__device__ float g_c1 [B_ * H1_];
__device__ float g_s1p[B_ * H1_];
__device__ float g_c3 [B_ * H1_];
__device__ float g_part2[SK2 * B_ * H2_];              // gemm2 split-K partials
__device__ __half g_b_frag[(size_t)D_ * H1_];          // W1 B-frags for jac/recover
__device__ float  g_w2_frag[H2_ * H1_];
__device__ __half g_c3_frag[B_ * H1_];
__device__ __half g_x_hi[(size_t)B_ * D_];             // x A-frags, hi/lo split
__device__ __half g_x_lo[(size_t)B_ * D_];
__device__ __half g_w1g1_hi[(size_t)H1_ * D_];         // W1 B-frags (gemm1 orient)
__device__ __half g_w1g1_lo[(size_t)H1_ * D_];

__device__ __forceinline__ float sigm(float v) { return 1.0f / (1.0f + expf(-v)); }

__device__ __forceinline__ uint32_t packh2(float a, float b) {
    __half2 t = __floats2half2_rn(a, b);
    return *reinterpret_cast<uint32_t*>(&t);
}
__device__ __forceinline__ void mma_f16(float* c, const uint32_t* a,
                                        uint32_t b0, uint32_t b1) {
    asm volatile("mma.sync.aligned.m16n8k16.row.col.f32.f16.f16.f32 "
                 "{%0,%1,%2,%3}, {%4,%5,%6,%7}, {%8,%9}, {%0,%1,%2,%3};"
                 : "+f"(c[0]), "+f"(c[1]), "+f"(c[2]), "+f"(c[3])
                 : "r"(a[0]), "r"(a[1]), "r"(a[2]), "r"(a[3]), "r"(b0), "r"(b1));
}

// ============================================================================
// x A-fragment pack with hi/lo fp16 split. Tiles [kt=64][mt=32], 512B each.
// ============================================================================
__global__ __launch_bounds__(256)
void x_frag_kernel(const float* __restrict__ x,
                   __half* __restrict__ xh, __half* __restrict__ xl) {
    const int t = blockIdx.x * 8 + (threadIdx.x >> 5);
    const int mt = t & 31, kt = t >> 5;
    const int lane = threadIdx.x & 31;
    const int r0 = mt * 16 + (lane >> 2);
    const int kb = kt * 16 + 2 * (lane & 3);
    const float* xa = x + (size_t)r0 * D_;
    const float* xb = xa + 8 * D_;
    float v[8] = {xa[kb], xa[kb + 1], xb[kb], xb[kb + 1],
                  xa[kb + 8], xa[kb + 9], xb[kb + 8], xb[kb + 9]};
    uint32_t hp[4], lp[4];
#pragma unroll
    for (int j = 0; j < 4; j++) {
        float a = v[2 * j], c = v[2 * j + 1];
        __half ha = __float2half_rn(a);
        __half hc = __float2half_rn(c);
        hp[j] = packh2(a, c);
        lp[j] = packh2(a - __half2float(ha), c - __half2float(hc));
    }
    *(uint4*)(xh + (size_t)t * 256 + lane * 8) = make_uint4(hp[0], hp[1], hp[2], hp[3]);
    *(uint4*)(xl + (size_t)t * 256 + lane * 8) = make_uint4(lp[0], lp[1], lp[2], lp[3]);
}

// ============================================================================
// W1 B-fragment pack for gemm1 (n=h1, k=d), hi/lo split. Tiles [n16=32][kt=64].
// ============================================================================
__global__ __launch_bounds__(256)
void w1g1_frag_kernel(const float* __restrict__ W1,
                      __half* __restrict__ wh, __half* __restrict__ wl) {
    const int t = blockIdx.x * 8 + (threadIdx.x >> 5);
    const int kt = t & 63, n16 = t >> 6;
    const int lane = threadIdx.x & 31;
    const int n0 = n16 * 16 + (lane >> 2);
    const int kb = kt * 16 + 2 * (lane & 3);
    const float* wa = W1 + (size_t)n0 * D_;
    const float* wb = wa + 8 * D_;
    float v[8] = {wa[kb], wa[kb + 1], wa[kb + 8], wa[kb + 9],
                  wb[kb], wb[kb + 1], wb[kb + 8], wb[kb + 9]};
    uint32_t hp[4], lp[4];
#pragma unroll
    for (int j = 0; j < 4; j++) {
        float a = v[2 * j], c = v[2 * j + 1];
        __half ha = __float2half_rn(a);
        __half hc = __float2half_rn(c);
        hp[j] = packh2(a, c);
        lp[j] = packh2(a - __half2float(ha), c - __half2float(hc));
    }
    const size_t off = ((size_t)n16 * 64 + kt) * 256 + lane * 8;
    *(uint4*)(wh + off) = make_uint4(hp[0], hp[1], hp[2], hp[3]);
    *(uint4*)(wl + off) = make_uint4(lp[0], lp[1], lp[2], lp[3]);
}

// ============================================================================
// gemm1 via mma.sync fp16 3-pass, prepped fragments. c1/s1p fused epilogue.
// CTA 32x64, warp tile 16x16, grid (8, 16) = 128 CTAs.
// ============================================================================
__global__ __launch_bounds__(256)
void gemm1_mma_kernel(const __half* __restrict__ xh, const __half* __restrict__ xl,
                      const __half* __restrict__ w1h, const __half* __restrict__ w1l,
                      const float* __restrict__ b1v,
                      float* __restrict__ c1, float* __restrict__ s1p) {
    const int tid = threadIdx.x;
    const int wid = tid >> 5;
    const int lane = tid & 31;
    const int wm = wid >> 2;
    const int wn = wid & 3;
    const int mtb = blockIdx.y * 2 + wm;
    const int n16 = blockIdx.x * 4 + wn;

    const __half* Ah = xh + (size_t)mtb * 256 + lane * 8;
    const __half* Al = xl + (size_t)mtb * 256 + lane * 8;
    const __half* Bh = w1h + (size_t)n16 * 64 * 256 + lane * 8;
    const __half* Bl = w1l + (size_t)n16 * 64 * 256 + lane * 8;

    float acc[2][4] = {};

    #pragma unroll 8
    for (int kt = 0; kt < 64; kt++) {
        uint4 ah = *(const uint4*)(Ah + (size_t)kt * 32 * 256);
        uint4 al = *(const uint4*)(Al + (size_t)kt * 32 * 256);
        uint4 bh = *(const uint4*)(Bh + (size_t)kt * 256);
        uint4 bl = *(const uint4*)(Bl + (size_t)kt * 256);
        const uint32_t* ap  = reinterpret_cast<const uint32_t*>(&ah);
        const uint32_t* alp = reinterpret_cast<const uint32_t*>(&al);
        mma_f16(acc[0], ap,  bh.x, bh.y);
        mma_f16(acc[1], ap,  bh.z, bh.w);
        mma_f16(acc[0], alp, bh.x, bh.y);
        mma_f16(acc[1], alp, bh.z, bh.w);
        mma_f16(acc[0], ap,  bl.x, bl.y);
        mma_f16(acc[1], ap,  bl.z, bl.w);
    }

    const int g = lane >> 2;
    const int cq = 2 * (lane & 3);
    const int r0 = mtb * 16 + g;
#pragma unroll
    for (int nt = 0; nt < 2; nt++) {
        const int col = n16 * 16 + nt * 8 + cq;
        const float b0 = b1v[col], b1c = b1v[col + 1];
        float cA = sigm(acc[nt][0] + b0);
        float cB = sigm(acc[nt][1] + b1c);
        float cC = sigm(acc[nt][2] + b0);
        float cD = sigm(acc[nt][3] + b1c);
        *(float2*)(c1  + (size_t)r0 * H1_ + col)       = make_float2(cA, cB);
        *(float2*)(c1  + (size_t)(r0 + 8) * H1_ + col) = make_float2(cC, cD);
        *(float2*)(s1p + (size_t)r0 * H1_ + col)       = make_float2(cA * (1.0f - cA), cB * (1.0f - cB));
        *(float2*)(s1p + (size_t)(r0 + 8) * H1_ + col) = make_float2(cC * (1.0f - cC), cD * (1.0f - cD));
    }
}

// ============================================================================
// B fragment pack: W1 -> g_b_frag (jac/recover orientation).
// ============================================================================
__global__ __launch_bounds__(256)
void w1_frag_kernel(const float* __restrict__ W1, __half* __restrict__ gB) {
    const int t = blockIdx.x * 8 + (threadIdx.x >> 5);
    const int n16 = t >> 5, kt = t & 31;
    const int lane = threadIdx.x & 31;
    const int n0 = n16 * 16 + (lane >> 2);
    const int kb = kt * 16 + 2 * (lane & 3);

    const float* Wk0 = W1 + (size_t)kb * D_;
    uint32_t p0 = packh2(Wk0[n0],              Wk0[D_ + n0]);
    uint32_t p1 = packh2(Wk0[8 * D_ + n0],     Wk0[9 * D_ + n0]);
    uint32_t p2 = packh2(Wk0[n0 + 8],          Wk0[D_ + n0 + 8]);
    uint32_t p3 = packh2(Wk0[8 * D_ + n0 + 8], Wk0[9 * D_ + n0 + 8]);

    *(uint4*)(gB + (size_t)t * 256 + lane * 8) = make_uint4(p0, p1, p2, p3);
}

// ============================================================================
// W2 fragment pre-permute (input-only, once).
// ============================================================================
__global__ __launch_bounds__(256)
void w2_frag_kernel(const float* __restrict__ W2, float* __restrict__ w2f) {
    const int kt = blockIdx.x;
    const int mt = threadIdx.x >> 5;
    const int lane = threadIdx.x & 31;
    const int r0 = mt * 16 + (lane >> 2);
    const int kb = kt * 16 + 2 * (lane & 3);
    const float* w2a = W2 + (size_t)r0 * H1_;
    const float* w2b = w2a + 8 * H1_;
    float* dst = w2f + ((size_t)kt * 8 + mt) * 256 + lane * 8;
    *(float4*)(dst)     = make_float4(w2a[kb],     w2a[kb + 1], w2b[kb],     w2b[kb + 1]);
    *(float4*)(dst + 4) = make_float4(w2a[kb + 8], w2a[kb + 9], w2b[kb + 8], w2b[kb + 9]);
}

// ============================================================================
// c3 fragment pack.
// ============================================================================
__global__ __launch_bounds__(256)
void c3_frag_kernel(const float* __restrict__ c3, __half* __restrict__ gA) {
    const int t = blockIdx.x * 8 + (threadIdx.x >> 5);
    const int kt = t >> 5, mt = t & 31;
    const int lane = threadIdx.x & 31;
    const int r0 = mt * 16 + (lane >> 2);
    const int kb = kt * 16 + 2 * (lane & 3);
    const float* ca = c3 + (size_t)r0 * H1_;
    const float* cb = ca + 8 * H1_;
    uint32_t p0 = packh2(ca[kb],     ca[kb + 1]);
    uint32_t p1 = packh2(cb[kb],     cb[kb + 1]);
    uint32_t p2 = packh2(ca[kb + 8], ca[kb + 9]);
    uint32_t p3 = packh2(cb[kb + 8], cb[kb + 9]);
    *(uint4*)(gA + (size_t)t * 256 + lane * 8) = make_uint4(p0, p1, p2, p3);
}

// ============================================================================
// Split-K partial SGEMM (TB), SK2-way: gemm2 (c1 @ W2^T) -> p2.
// grid (N/64, M/64, SK2) = (2, 8, 8) = 128 CTAs; K chunk = 64, NT = 4.
// ============================================================================
__global__ __launch_bounds__(256)
void sgemm_part_kernel(const float* __restrict__ A, const float* __restrict__ Bm,
                       float* __restrict__ P, int M, int N, int K) {
    constexpr int BM = 64, BN = 64, BK = 16;
    __shared__ __align__(16) float As[BK][BM + 4];
    __shared__ __align__(16) float Bs[BK][BN + 4];

    const int tid = threadIdx.x;
    const int m0 = blockIdx.y * BM;
    const int n0 = blockIdx.x * BN;
    const int kbase = blockIdx.z * (K / SK2);

    const int ak = tid & 15;
    const int am = tid >> 4;
    const int rowBase = (tid >> 4) * 4;
    const int colBase = (tid & 15) * 4;

    float acc[4][4] = {};
    float ra[4], rb[4];
    const int NT = (K / SK2) / BK;

    auto loadA = [&](int t) {
        const int kt = kbase + t * BK;
#pragma unroll
        for (int j = 0; j < 4; j++)
            ra[j] = A[(size_t)(m0 + am + 16 * j) * K + kt + ak];
    };
    auto loadB = [&](int t) {
        const int kt = kbase + t * BK;
#pragma unroll
        for (int j = 0; j < 4; j++)
            rb[j] = Bm[(size_t)(n0 + am + 16 * j) * K + kt + ak];
    };
    auto storeAB = [&]() {
#pragma unroll
        for (int j = 0; j < 4; j++) As[ak][am + 16 * j] = ra[j];
#pragma unroll
        for (int j = 0; j < 4; j++) Bs[ak][am + 16 * j] = rb[j];
    };

    loadA(0); loadB(0);
    storeAB();
    __syncthreads();

    for (int t = 0; t < NT; t++) {
        if (t + 1 < NT) { loadA(t + 1); loadB(t + 1); }
#pragma unroll
        for (int kk = 0; kk < BK; kk++) {
            float a[4], bq[4];
            *(float4*)a  = *(const float4*)&As[kk][rowBase];
            *(float4*)bq = *(const float4*)&Bs[kk][colBase];
#pragma unroll
            for (int i = 0; i < 4; i++)
#pragma unroll
                for (int j = 0; j < 4; j++)
                    acc[i][j] += a[i] * bq[j];
        }
        __syncthreads();
        if (t + 1 < NT) { storeAB(); __syncthreads(); }
    }

    float* Pz = P + (size_t)blockIdx.z * M * N;
#pragma unroll
    for (int i = 0; i < 4; i++) {
        const int row = m0 + rowBase + i;
#pragma unroll
        for (int j = 0; j < 4; j++)
            Pz[(size_t)row * N + n0 + colBase + j] = acc[i][j];
    }
}

// ============================================================================
// Reduce SK2 partials + bias -> sigmoid (c2 output, on s1).
// ============================================================================
__global__ __launch_bounds__(256)
void reduce_act_kernel(const float* __restrict__ P, const float* __restrict__ bias,
                       float* __restrict__ C, int MN, int Nmask) {
    const int idx = (blockIdx.x * 256 + threadIdx.x) * 4;
    float4 s = *(const float4*)(P + idx);
#pragma unroll
    for (int z = 1; z < SK2; z++) {
        float4 v = *(const float4*)(P + (size_t)z * MN + idx);
        s.x += v.x; s.y += v.y; s.z += v.z; s.w += v.w;
    }
    float4 bb = *(const float4*)(bias + (idx & Nmask));
    float4 c;
    c.x = sigm(s.x + bb.x);
    c.y = sigm(s.y + bb.y);
    c.z = sigm(s.z + bb.z);
    c.w = sigm(s.w + bb.w);
    *(float4*)(C + idx) = c;
}

// ============================================================================
// Jac GEMM — R14 version (warp 64x64, CTA 128x256, 1 CTA/SM). s1p loaded
// directly; s2p from SK2 partials in prologue. grid (4, 512).
// ============================================================================
__global__ __launch_bounds__(256, 1)
void jac_mma_kernel(const float* __restrict__ w2f,
                    const float* __restrict__ s1p,
                    const float* __restrict__ p2, const float* __restrict__ b2v,
                    const __half* __restrict__ gB,
                    float* __restrict__ jac) {
    __shared__ float ss[H1_];
    __shared__ float s2s[H2_];
    constexpr int MN2 = B_ * H2_;
    const int tid = threadIdx.x;
    const int wid = tid >> 5;
    const int lane = tid & 31;
    const int wm = wid >> 2;
    const int wn = wid & 3;
    const int b  = blockIdx.y;
    const int n0 = blockIdx.x * 256;

    for (int i = tid; i < H1_; i += 256) ss[i] = s1p[(size_t)b * H1_ + i];
    if (tid < H2_) {
        const int off = b * H2_ + tid;
        float v = p2[off];
#pragma unroll
        for (int z = 1; z < SK2; z++) v += p2[(size_t)z * MN2 + off];
        v += b2v[tid];
        float c = sigm(v);
        s2s[tid] = c * (1.0f - c);
    }
    __syncthreads();

    const float* Aw = w2f + (size_t)(wm * 4) * 256 + lane * 8;
    const __half* Bb = gB + (size_t)((n0 >> 4) + wn * 4) * (32 * 256) + lane * 8;
    const int klo = 2 * (lane & 3);

    float acc[4][8][4] = {};

    #pragma unroll 2
    for (int kt = 0; kt < 32; kt++) {
        const int kb = kt * 16 + klo;
        const float s0 = ss[kb], s1v = ss[kb + 1];
        const float s8 = ss[kb + 8], s9 = ss[kb + 9];

        uint32_t a[4][4];
        uint4 bv[4];
#pragma unroll
        for (int mt = 0; mt < 4; mt++) {
            const float* src = Aw + ((size_t)kt * 8 + mt) * 256;
            float4 f0 = *(const float4*)(src);
            float4 f1 = *(const float4*)(src + 4);
            a[mt][0] = packh2(f0.x * s0, f0.y * s1v);
            a[mt][1] = packh2(f0.z * s0, f0.w * s1v);
            a[mt][2] = packh2(f1.x * s8, f1.y * s9);
            a[mt][3] = packh2(f1.z * s8, f1.w * s9);
        }
#pragma unroll
        for (int np = 0; np < 4; np++)
            bv[np] = *(const uint4*)(Bb + ((size_t)np * 32 + kt) * 256);
#pragma unroll
        for (int mt = 0; mt < 4; mt++) {
#pragma unroll
            for (int np = 0; np < 4; np++) {
                mma_f16(acc[mt][np * 2 + 0], a[mt], bv[np].x, bv[np].y);
                mma_f16(acc[mt][np * 2 + 1], a[mt], bv[np].z, bv[np].w);
            }
        }
    }

    const int g = lane >> 2;
    const int cq = 2 * (lane & 3);
#pragma unroll
    for (int mt = 0; mt < 4; mt++) {
        const int r0 = wm * 64 + mt * 16 + g;
        const float s0 = s2s[r0];
        const float s1 = s2s[r0 + 8];
        float* row0 = jac + ((size_t)b * H2_ + r0) * D_ + n0;
        float* row1 = row0 + 8 * D_;
#pragma unroll
        for (int nt = 0; nt < 8; nt++) {
            const int col = wn * 64 + nt * 8 + cq;
            *(float2*)(row0 + col) = make_float2(acc[mt][nt][0] * s0, acc[mt][nt][1] * s0);
            *(float2*)(row1 + col) = make_float2(acc[mt][nt][2] * s1, acc[mt][nt][3] * s1);
        }
    }
}

// ============================================================================
// recover = c3 @ W1 + b_r via fragment-direct mma; reuses g_b_frag.
// ============================================================================
__global__ __launch_bounds__(256, 1)
void recover_mma_kernel(const __half* __restrict__ gA,
                        const __half* __restrict__ gB,
                        const float* __restrict__ b_r,
                        float* __restrict__ out) {
    const int tid = threadIdx.x;
    const int wid = tid >> 5;
    const int lane = tid & 31;
    const int wm = wid >> 2;
    const int wn = wid & 3;
    const int m0 = blockIdx.y * 128;
    const int n0 = blockIdx.x * 256;

    const int mtb = (m0 >> 4) + wm * 4;
    const int n16base = (n0 >> 4) + wn * 4;

    float acc[4][8][4] = {};

    #pragma unroll 2
    for (int kt = 0; kt < 32; kt++) {
        uint4 av[4], bv[4];
#pragma unroll
        for (int mt = 0; mt < 4; mt++)
            av[mt] = *(const uint4*)(gA + ((size_t)kt * 32 + mtb + mt) * 256
                                     + lane * 8);
#pragma unroll
        for (int np = 0; np < 4; np++)
            bv[np] = *(const uint4*)(gB + ((size_t)(n16base + np) * 32 + kt) * 256
                                     + lane * 8);
#pragma unroll
        for (int mt = 0; mt < 4; mt++) {
            const uint32_t* ap = reinterpret_cast<const uint32_t*>(&av[mt]);
#pragma unroll
            for (int np = 0; np < 4; np++) {
                mma_f16(acc[mt][np * 2 + 0], ap, bv[np].x, bv[np].y);
                mma_f16(acc[mt][np * 2 + 1], ap, bv[np].z, bv[np].w);
            }
        }
    }

    const int g = lane >> 2;
    const int cq = 2 * (lane & 3);
#pragma unroll
    for (int mt = 0; mt < 4; mt++) {
        const int r0 = m0 + wm * 64 + mt * 16 + g;
        float* row0 = out + (size_t)r0 * D_ + n0;
        float* row1 = row0 + 8 * D_;
#pragma unroll
        for (int nt = 0; nt < 8; nt++) {
            const int col = wn * 64 + nt * 8 + cq;
            const float bc0 = b_r[n0 + col], bc1 = b_r[n0 + col + 1];
            *(float2*)(row0 + col) = make_float2(acc[mt][nt][0] + bc0, acc[mt][nt][1] + bc1);
            *(float2*)(row1 + col) = make_float2(acc[mt][nt][2] + bc0, acc[mt][nt][3] + bc1);
        }
    }
}

// ============================================================================
// Plain scalar SGEMM (gemm3: c3 = sigmoid(c2 @ W2 + b3), K=128).
// ============================================================================
__global__ __launch_bounds__(256)
void sgemm_nn_kernel(const float* __restrict__ A, const float* __restrict__ Bm,
                     const float* __restrict__ bias, float* __restrict__ C,
                     int M, int N, int K) {
    constexpr int BM = 64, BN = 64, BK = 16;
    __shared__ __align__(16) float As[BK][BM + 4];
    __shared__ __align__(16) float Bs[BK][BN + 4];

    const int tid = threadIdx.x;
    const int m0 = blockIdx.y * BM;
    const int n0 = blockIdx.x * BN;

    const int ak = tid & 15;
    const int am = tid >> 4;
    const int rowBase = (tid >> 4) * 4;
    const int colBase = (tid & 15) * 4;

    float acc[4][4] = {};
    float ra[4], rb[4];
    const int NT = K / BK;

    auto loadA = [&](int t) {
        const int kt = t * BK;
#pragma unroll
        for (int j = 0; j < 4; j++)
            ra[j] = A[(size_t)(m0 + am + 16 * j) * K + kt + ak];
    };
    auto loadB = [&](int t) {
        const int kt = t * BK;
#pragma unroll
        for (int j = 0; j < 4; j++)
            rb[j] = Bm[(size_t)(kt + (tid >> 6) + 4 * j) * N + n0 + (tid & 63)];
    };
    auto storeAB = [&]() {
#pragma unroll
        for (int j = 0; j < 4; j++) As[ak][am + 16 * j] = ra[j];
#pragma unroll
        for (int j = 0; j < 4; j++) Bs[(tid >> 6) + 4 * j][tid & 63] = rb[j];
    };

    loadA(0); loadB(0);
    storeAB();
    __syncthreads();

    for (int t = 0; t < NT; t++) {
        if (t + 1 < NT) { loadA(t + 1); loadB(t + 1); }
#pragma unroll
        for (int kk = 0; kk < BK; kk++) {
            float a[4], bq[4];
            *(float4*)a  = *(const float4*)&As[kk][rowBase];
            *(float4*)bq = *(const float4*)&Bs[kk][colBase];
#pragma unroll
            for (int i = 0; i < 4; i++)
#pragma unroll
                for (int j = 0; j < 4; j++)
                    acc[i][j] += a[i] * bq[j];
        }
        __syncthreads();
        if (t + 1 < NT) { storeAB(); __syncthreads(); }
    }

#pragma unroll
    for (int i = 0; i < 4; i++) {
        const int row = m0 + rowBase + i;
#pragma unroll
        for (int j = 0; j < 4; j++) {
            const int col = n0 + colBase + j;
            C[(size_t)row * N + col] = sigm(acc[i][j] + bias[col]);
        }
    }
}

// ============================================================================
// Streams/events (created once, on the first — non-captured — call).
// ============================================================================
struct Aux {
    cudaStream_t s1;
    cudaEvent_t e0, eg1, ew, ep2, etail;
    Aux() {
        cudaStreamCreateWithFlags(&s1, cudaStreamNonBlocking);
        cudaEventCreateWithFlags(&e0,   cudaEventDisableTiming);
        cudaEventCreateWithFlags(&eg1,  cudaEventDisableTiming);
        cudaEventCreateWithFlags(&ew,   cudaEventDisableTiming);
        cudaEventCreateWithFlags(&ep2,  cudaEventDisableTiming);
        cudaEventCreateWithFlags(&etail, cudaEventDisableTiming);
    }
};

extern "C" void kernel_launch(void* const* d_in, const int* in_sizes, int n_in,
                              void* d_out, int out_size) {
    const float* x   = (const float*)d_in[0];
    const float* W1  = (const float*)d_in[1];
    const float* b1  = (const float*)d_in[2];
    const float* W2  = (const float*)d_in[3];
    const float* b2  = (const float*)d_in[4];
    const float* b3  = (const float*)d_in[5];
    const float* b_r = (const float*)d_in[6];

    float* out     = (float*)d_out;
    float* recover = out;
    float* c2      = out + (size_t)B_ * D_;
    float* jac     = c2 + (size_t)B_ * H2_;

    float *c1, *s1p, *c3, *w2f, *p2;
    __half *b_frag, *c3_frag, *xh, *xl, *w1g1h, *w1g1l;
    cudaGetSymbolAddress((void**)&c1,  g_c1);
    cudaGetSymbolAddress((void**)&s1p, g_s1p);
    cudaGetSymbolAddress((void**)&c3,  g_c3);
    cudaGetSymbolAddress((void**)&w2f, g_w2_frag);
    cudaGetSymbolAddress((void**)&p2,  g_part2);
    cudaGetSymbolAddress((void**)&b_frag, g_b_frag);
    cudaGetSymbolAddress((void**)&c3_frag, g_c3_frag);
    cudaGetSymbolAddress((void**)&xh, g_x_hi);
    cudaGetSymbolAddress((void**)&xl, g_x_lo);
    cudaGetSymbolAddress((void**)&w1g1h, g_w1g1_hi);
    cudaGetSymbolAddress((void**)&w1g1l, g_w1g1_lo);

    static Aux aux;
    cudaStream_t s0 = 0, s1 = aux.s1;
    dim3 blk(256);

    // fork
    cudaEventRecord(aux.e0, s0);
    cudaStreamWaitEvent(s1, aux.e0, 0);

    // s1: input-only fragment preps (gemm1 B first — needed earliest)
    w1g1_frag_kernel<<<256, blk, 0, s1>>>(W1, w1g1h, w1g1l);
    cudaEventRecord(aux.eg1, s1);
    w1_frag_kernel<<<(64 * 32) / 8, blk, 0, s1>>>(W1, b_frag);
    w2_frag_kernel<<<32, blk, 0, s1>>>(W2, w2f);
    cudaEventRecord(aux.ew, s1);

    // s0: x fragments, then gemm1 on HMMA -> c1, s1p
    x_frag_kernel<<<256, blk, 0, s0>>>(x, xh, xl);
    cudaStreamWaitEvent(s0, aux.eg1, 0);
    gemm1_mma_kernel<<<dim3(8, 16), blk, 0, s0>>>(xh, xl, w1g1h, w1g1l,
                                                  b1, c1, s1p);

    // s0: gemm2 split-K (8-way, grid 128) -> p2
    sgemm_part_kernel<<<dim3(H2_ / 64, B_ / 64, SK2), blk, 0, s0>>>(
        c1, W2, p2, B_, H2_, H1_);
    cudaEventRecord(aux.ep2, s0);

    // s1 tail: c2 output -> c3 chain -> recover (hidden under jac)
    cudaStreamWaitEvent(s1, aux.ep2, 0);
    reduce_act_kernel<<<(B_ * H2_) / 1024, blk, 0, s1>>>(
        p2, b2, c2, B_ * H2_, H2_ - 1);
    sgemm_nn_kernel<<<dim3(H1_ / 64, B_ / 64), blk, 0, s1>>>(
        c2, W2, b3, c3, B_, H1_, H2_);
    c3_frag_kernel<<<(32 * 32) / 8, blk, 0, s1>>>(c3, c3_frag);
    recover_mma_kernel<<<dim3(D_ / 256, B_ / 128), blk, 0, s1>>>(
        c3_frag, b_frag, b_r, recover);
    cudaEventRecord(aux.etail, s1);

    // s0: jac (s1p direct; s2p from p2 in prologue)
    cudaStreamWaitEvent(s0, aux.ew, 0);
    jac_mma_kernel<<<dim3(D_ / 256, B_), blk, 0, s0>>>(
        w2f, s1p, p2, b2, b_frag, jac);

    // join
    cudaStreamWaitEvent(s0, aux.etail, 0);
}